// round 4
// baseline (speedup 1.0000x reference)
#include <cuda_runtime.h>

#define BDIM 4096   // batch
#define IDIM 4096   // in features
#define ODIM 4096   // out features

// Scratch (allocation-free rule: __device__ globals)
__device__ float g_xs[BDIM];    // row sums of input
__device__ float g_wsb[ODIM];   // row sums of weight * bias

// ---------------------------------------------------------------------------
// Kernel 1: row sums. gridDim.x = BDIM + ODIM. Block r < BDIM sums input row r;
// block r >= BDIM sums weight row (r - BDIM) and multiplies by bias.
// 128 threads/block, each thread reads 8 float4 (32 floats) -> 4096 floats/row.
// ---------------------------------------------------------------------------
__global__ __launch_bounds__(128) void rowsum_kernel(
    const float* __restrict__ input,
    const float* __restrict__ weight,
    const float* __restrict__ bias)
{
    const int row = blockIdx.x;
    const int tid = threadIdx.x;

    const bool is_w = (row >= BDIM);
    const float4* src = reinterpret_cast<const float4*>(
        is_w ? (weight + (size_t)(row - BDIM) * IDIM)
             : (input  + (size_t)row * IDIM));

    // 4096 floats = 1024 float4; 128 threads -> 8 float4 each, coalesced stride.
    float s = 0.0f;
#pragma unroll
    for (int i = 0; i < 8; i++) {
        float4 v = src[tid + i * 128];
        s += (v.x + v.y) + (v.z + v.w);
    }

    // warp reduce
#pragma unroll
    for (int off = 16; off > 0; off >>= 1)
        s += __shfl_down_sync(0xFFFFFFFFu, s, off);

    __shared__ float warp_sums[4];
    if ((tid & 31) == 0) warp_sums[tid >> 5] = s;
    __syncthreads();

    if (tid == 0) {
        float total = warp_sums[0] + warp_sums[1] + warp_sums[2] + warp_sums[3];
        if (is_w) {
            int o = row - BDIM;
            g_wsb[o] = total * bias[o];
        } else {
            g_xs[row] = total;
        }
    }
}

// ---------------------------------------------------------------------------
// Kernel 2: out[b,o] = xs[b]*bias[o] + wsb[o], one float4 per thread.
// 4096*4096/4 = 4,194,304 float4 = 16384 blocks * 256 threads.
// xs[b] is uniform within a 256-thread stretch (1024 float4 per row), so the
// load broadcasts; bias/wsb are 16 KB each -> fully L2 (and mostly L1) resident.
// Kernel is pure STG bandwidth.
// ---------------------------------------------------------------------------
__global__ __launch_bounds__(256) void expand_kernel(
    const float* __restrict__ bias,
    float* __restrict__ out)
{
    const int idx = blockIdx.x * 256 + threadIdx.x;   // float4 index
    const int b  = idx >> 10;                         // / (ODIM/4)
    const int o4 = idx & 1023;                        // float4 col

    const float xs = g_xs[b];
    float4 bi  = reinterpret_cast<const float4*>(bias)[o4];
    float4 ws  = reinterpret_cast<const float4*>(g_wsb)[o4];

    float4 r;
    r.x = fmaf(xs, bi.x, ws.x);
    r.y = fmaf(xs, bi.y, ws.y);
    r.z = fmaf(xs, bi.z, ws.z);
    r.w = fmaf(xs, bi.w, ws.w);

    reinterpret_cast<float4*>(out)[idx] = r;
}

extern "C" void kernel_launch(void* const* d_in, const int* in_sizes, int n_in,
                              void* d_out, int out_size)
{
    const float* input  = (const float*)d_in[0];
    const float* weight = (const float*)d_in[1];
    const float* bias   = (const float*)d_in[2];
    float* out = (float*)d_out;

    rowsum_kernel<<<BDIM + ODIM, 128>>>(input, weight, bias);
    expand_kernel<<<(BDIM * ODIM / 4) / 256, 256>>>(bias, out);
}

// round 5
// speedup vs baseline: 1.0847x; 1.0847x over previous
#include <cuda_runtime.h>

#define BDIM 4096   // batch
#define IDIM 4096   // in features
#define ODIM 4096   // out features

// Scratch (allocation-free rule: __device__ global)
__device__ float g_wsb[ODIM];   // row sums of weight * bias

// ---------------------------------------------------------------------------
// Kernel W: wsb[o] = bias[o] * sum_i weight[o,i]
// One 128-thread block per weight row; 8 float4 per thread (4096 floats/row).
// Weight is read with DEFAULT cache policy so it tends to stay L2-resident
// across graph replays (input/output use streaming hints in kernel F).
// ---------------------------------------------------------------------------
__global__ __launch_bounds__(128) void wsum_kernel(
    const float* __restrict__ weight,
    const float* __restrict__ bias)
{
    const int row = blockIdx.x;
    const int tid = threadIdx.x;
    const float4* src = reinterpret_cast<const float4*>(weight + (size_t)row * IDIM);

    float4 v[8];
#pragma unroll
    for (int i = 0; i < 8; i++) v[i] = src[tid + i * 128];

    float s = 0.0f;
#pragma unroll
    for (int i = 0; i < 8; i++) s += (v[i].x + v[i].y) + (v[i].z + v[i].w);

#pragma unroll
    for (int off = 16; off > 0; off >>= 1)
        s += __shfl_down_sync(0xFFFFFFFFu, s, off);

    __shared__ float warp_sums[4];
    if ((tid & 31) == 0) warp_sums[tid >> 5] = s;
    __syncthreads();

    if (tid == 0) {
        float total = (warp_sums[0] + warp_sums[1]) + (warp_sums[2] + warp_sums[3]);
        g_wsb[row] = total * bias[row];
    }
}

// ---------------------------------------------------------------------------
// Kernel F (fused): per input row b:
//   xs = sum_i input[b,i]          (streaming loads — no L2 reuse, evict-first)
//   out[b,:] = xs * bias + wsb     (streaming stores — drain to DRAM, keep L2
//                                   free for the weight tensor)
// Reads and writes interleave across blocks, keeping DRAM busy the whole time
// instead of idling during a separate expand pass.
// ---------------------------------------------------------------------------
__global__ __launch_bounds__(128) void fused_kernel(
    const float* __restrict__ input,
    const float* __restrict__ bias,
    float* __restrict__ out)
{
    const int row = blockIdx.x;
    const int tid = threadIdx.x;

    const float4* src = reinterpret_cast<const float4*>(input + (size_t)row * IDIM);

    // Load phase: 8 independent LDG.128 (streaming) -> high MLP
    float4 v[8];
#pragma unroll
    for (int i = 0; i < 8; i++) v[i] = __ldcs(&src[tid + i * 128]);

    float s = 0.0f;
#pragma unroll
    for (int i = 0; i < 8; i++) s += (v[i].x + v[i].y) + (v[i].z + v[i].w);

#pragma unroll
    for (int off = 16; off > 0; off >>= 1)
        s += __shfl_down_sync(0xFFFFFFFFu, s, off);

    __shared__ float warp_sums[4];
    __shared__ float xs_sh;
    if ((tid & 31) == 0) warp_sums[tid >> 5] = s;
    __syncthreads();
    if (tid == 0)
        xs_sh = (warp_sums[0] + warp_sums[1]) + (warp_sums[2] + warp_sums[3]);
    __syncthreads();
    const float xs = xs_sh;

    // Store phase: out[b, o] = xs * bias[o] + wsb[o]
    // bias/wsb are 16 KB each -> L1/L2 resident broadcast loads.
    float4* dst = reinterpret_cast<float4*>(out + (size_t)row * ODIM);
    const float4* bi4 = reinterpret_cast<const float4*>(bias);
    const float4* ws4 = reinterpret_cast<const float4*>(g_wsb);

#pragma unroll
    for (int i = 0; i < 8; i++) {
        const int c = tid + i * 128;
        float4 b = bi4[c];
        float4 w = ws4[c];
        float4 r;
        r.x = fmaf(xs, b.x, w.x);
        r.y = fmaf(xs, b.y, w.y);
        r.z = fmaf(xs, b.z, w.z);
        r.w = fmaf(xs, b.w, w.w);
        __stcs(&dst[c], r);
    }
}

extern "C" void kernel_launch(void* const* d_in, const int* in_sizes, int n_in,
                              void* d_out, int out_size)
{
    const float* input  = (const float*)d_in[0];
    const float* weight = (const float*)d_in[1];
    const float* bias   = (const float*)d_in[2];
    float* out = (float*)d_out;

    wsum_kernel<<<ODIM, 128>>>(weight, bias);
    fused_kernel<<<BDIM, 128>>>(input, bias, out);
}